// round 2
// baseline (speedup 1.0000x reference)
#include <cuda_runtime.h>
#include <cuda_bf16.h>
#include <math.h>

// ---------------- problem constants ----------------
#define B_SZ 8
#define P_SZ 4096
#define NPATH (B_SZ * P_SZ)      // 32768
#define S_SZ 16
#define NFIB 128
#define NBAND 10
#define NFREQ 512
#define FLEN 1023
#define RIRLEN 96000
#define EPS 1e-9f
#define TWO_PI_D 6.283185307179586

// ---------------- device scratch (statics are the sanctioned scratch) ------
__device__ float g_cosW[512 * 512];     // cos(2*pi*k*n/1023), k,n < 512
__device__ float g_sinW[512 * 512];     // sin(2*pi*k*n/1023)
__device__ float g_T[20 * 512];         // time-domain of interp rows (n<512)
__device__ float g_G[20 * 512];         // phase map: phase[q] = c . G[:,q]
__device__ float g_logrefl[S_SZ * NBAND];
__device__ float g_sigdir[NFIB * NBAND];
__device__ float g_re[NPATH * 512];     // weighted Re of fr (gain, 1/N, x2 folded)
__device__ float g_im[NPATH * 512];     // weighted Im of fr
__device__ float g_C[NPATH * 512];      // sum Re*cos
__device__ float g_S[NPATH * 512];      // sum Im*sin
__device__ float g_rir[B_SZ * RIRLEN];

// ---------------- precompute kernels ----------------
__global__ void zero_rir_kernel() {
    int i = blockIdx.x * blockDim.x + threadIdx.x;
    if (i < B_SZ * RIRLEN) g_rir[i] = 0.f;
}

__global__ void pre_small_kernel(const float* __restrict__ sp,
                                 const float* __restrict__ dp) {
    int i = blockIdx.x * blockDim.x + threadIdx.x;
    if (i < S_SZ * NBAND) {
        float s = 1.f / (1.f + expf(-sp[i]));
        g_logrefl[i] = logf(s <= EPS ? EPS : s);
    }
    if (i < NFIB * NBAND) {
        g_sigdir[i] = 1.f / (1.f + expf(-dp[i]));
    }
}

__global__ void pre_twiddle_kernel() {
    int i = blockIdx.x * blockDim.x + threadIdx.x;
    if (i >= 512 * 512) return;
    int k = i >> 9, n = i & 511;
    long long m = ((long long)k * (long long)n) % FLEN;
    double ang = (double)m * (TWO_PI_D / (double)FLEN);
    g_cosW[i] = (float)cos(ang);
    g_sinW[i] = (float)sin(ang);
}

// T[j][n] = row[0] + 2*sum_{k=1}^{511} row[k]*cos(2 pi k n / N)   (n < 512)
__global__ void pre_T_kernel(const float* __restrict__ surf_interp,
                             const float* __restrict__ dir_interp) {
    int i = blockIdx.x * blockDim.x + threadIdx.x;
    if (i >= 20 * 512) return;
    int j = i >> 9, n = i & 511;
    const float* row = (j < 10) ? (surf_interp + j * 512) : (dir_interp + (j - 10) * 512);
    float acc = row[0];
    for (int k = 1; k < 512; k++) acc += 2.f * row[k] * g_cosW[k * 512 + n];
    g_T[i] = acc;
}

// G[j][q] = -(2/N) * sum_{n=1}^{511} T[j][n] * sin(2 pi q n / N)
__global__ void pre_G_kernel() {
    int i = blockIdx.x * blockDim.x + threadIdx.x;
    if (i >= 20 * 512) return;
    int j = i >> 9, q = i & 511;
    float acc = 0.f;
    for (int n = 1; n < 512; n++) acc += g_T[j * 512 + n] * g_sinW[n * 512 + q];
    g_G[i] = acc * (-2.f / (float)FLEN);
}

// ---------------- per-path spectrum kernel ----------------
__global__ void __launch_bounds__(128) fr_kernel(
    const float* __restrict__ path_dirs,
    const float* __restrict__ surf_interp,
    const float* __restrict__ dir_interp,
    const float* __restrict__ fib,
    const int* __restrict__ mask,
    const int* __restrict__ delays) {
    int path = blockIdx.x;
    int t = threadIdx.x;

    __shared__ float sh_c[20];
    __shared__ float sh_w[128];
    __shared__ float sh_red[8];

    // surface coefficients
    if (t < NBAND) {
        const int* m = mask + path * S_SZ;
        float acc = 0.f;
#pragma unroll
        for (int s = 0; s < S_SZ; s++) acc += (float)m[s] * g_logrefl[s * NBAND + t];
        sh_c[t] = acc;
    }

    // normalized direction
    float dx = path_dirs[path * 3 + 0];
    float dy = path_dirs[path * 3 + 1];
    float dz = path_dirs[path * 3 + 2];
    float inv = 1.f / (sqrtf(dx * dx + dy * dy + dz * dz) + EPS);
    dx *= inv; dy *= inv; dz *= inv;

    // logits over 128 fib points (blockDim == 128)
    float logit = 8.f * (dx * fib[t * 3 + 0] + dy * fib[t * 3 + 1] + dz * fib[t * 3 + 2]);

    // block max
    float v = logit;
#pragma unroll
    for (int o = 16; o; o >>= 1) v = fmaxf(v, __shfl_xor_sync(0xffffffffu, v, o));
    if ((t & 31) == 0) sh_red[t >> 5] = v;
    __syncthreads();
    float mx = fmaxf(fmaxf(sh_red[0], sh_red[1]), fmaxf(sh_red[2], sh_red[3]));
    float e = expf(logit - mx);
    v = e;
#pragma unroll
    for (int o = 16; o; o >>= 1) v += __shfl_xor_sync(0xffffffffu, v, o);
    if ((t & 31) == 0) sh_red[4 + (t >> 5)] = v;
    __syncthreads();
    float tot = sh_red[4] + sh_red[5] + sh_red[6] + sh_red[7];
    sh_w[t] = e / tot;
    __syncthreads();

    if (t < NBAND) {
        float amp = 0.f;
        for (int n = 0; n < NFIB; n++) amp += sh_w[n] * g_sigdir[n * NBAND + t];
        sh_c[10 + t] = logf(amp <= EPS ? EPS : amp);
    }
    __syncthreads();

    int dly = delays[path];
    float gain = 1.f / fmaxf((float)dly * (1.f / 48.f), 1.f);
    float base_scale = gain * (1.f / (float)FLEN);

    for (int q = t; q < 512; q += 128) {
        float la = 0.f, ph = 0.f;
#pragma unroll
        for (int j = 0; j < 10; j++) la += sh_c[j] * surf_interp[j * 512 + q];
#pragma unroll
        for (int j = 0; j < 10; j++) la += sh_c[10 + j] * dir_interp[j * 512 + q];
#pragma unroll
        for (int j = 0; j < 20; j++) ph += sh_c[j] * g_G[j * 512 + q];
        float a = expf(la) * base_scale * (q == 0 ? 1.f : 2.f);
        float sn, cs;
        sincosf(ph, &sn, &cs);
        g_re[path * 512 + q] = a * cs;
        g_im[path * 512 + q] = -a * sn;
    }
}

// ---------------- DFT as SGEMM: C = Re*cosW, S = Im*sinW ----------------
#define GM 128
#define GN 128
#define GK 8
__global__ void __launch_bounds__(256) dft_gemm_kernel() {
    int zsel = blockIdx.z;
    const float* __restrict__ A = zsel ? g_im : g_re;     // [32768][512]
    const float* __restrict__ Bm = zsel ? g_sinW : g_cosW; // [512][512]
    float* __restrict__ Cp = zsel ? g_S : g_C;

    __shared__ float As[GK][GM];
    __shared__ float Bs[GK][GN];

    int tid = threadIdx.x;
    int tx = tid & 15;
    int ty = tid >> 4;
    int rowBase = blockIdx.y * GM;
    int colBase = blockIdx.x * GN;

    float acc[8][8];
#pragma unroll
    for (int i = 0; i < 8; i++)
#pragma unroll
        for (int j = 0; j < 8; j++) acc[i][j] = 0.f;

    int aRow = tid >> 1;
    int aK = (tid & 1) * 4;
    int bK = tid >> 5;
    int bCol = (tid & 31) * 4;

    const float* Aptr = A + (size_t)(rowBase + aRow) * 512 + aK;
    const float* Bptr = Bm + (size_t)bK * 512 + colBase + bCol;

    for (int k0 = 0; k0 < 512; k0 += GK) {
        float4 av = *(const float4*)(Aptr + k0);
        float4 bv = *(const float4*)(Bptr + (size_t)k0 * 512);
        As[aK + 0][aRow] = av.x;
        As[aK + 1][aRow] = av.y;
        As[aK + 2][aRow] = av.z;
        As[aK + 3][aRow] = av.w;
        *(float4*)&Bs[bK][bCol] = bv;
        __syncthreads();
#pragma unroll
        for (int kk = 0; kk < GK; kk++) {
            float a[8], b[8];
            *(float4*)&a[0] = *(const float4*)&As[kk][ty * 8];
            *(float4*)&a[4] = *(const float4*)&As[kk][ty * 8 + 4];
            *(float4*)&b[0] = *(const float4*)&Bs[kk][tx * 8];
            *(float4*)&b[4] = *(const float4*)&Bs[kk][tx * 8 + 4];
#pragma unroll
            for (int i = 0; i < 8; i++)
#pragma unroll
                for (int j = 0; j < 8; j++) acc[i][j] += a[i] * b[j];
        }
        __syncthreads();
    }
#pragma unroll
    for (int i = 0; i < 8; i++) {
        float* dst = Cp + (size_t)(rowBase + ty * 8 + i) * 512 + colBase + tx * 8;
        float4 v0 = make_float4(acc[i][0], acc[i][1], acc[i][2], acc[i][3]);
        float4 v1 = make_float4(acc[i][4], acc[i][5], acc[i][6], acc[i][7]);
        *(float4*)(dst) = v0;
        *(float4*)(dst + 4) = v1;
    }
}

// ---------------- combine + scatter into RIR ----------------
__global__ void __launch_bounds__(256) scatter_kernel(const int* __restrict__ delays) {
    int path = blockIdx.x;
    int t = threadIdx.x;
    int b = path >> 12;  // / 4096
    int dly = delays[path];
    float* rir = g_rir + (size_t)b * RIRLEN + dly;
    for (int n = t; n < 512; n += 256) {
        float c = g_C[(size_t)path * 512 + n];
        float s = g_S[(size_t)path * 512 + n];
        atomicAdd(&rir[n], c - s);          // filt[n]
        if (n) atomicAdd(&rir[FLEN - n], c + s);  // filt[1023-n]
    }
}

// ---------------- 'same' cross-correlation with source kernel ----------------
// out[b][t] = sum_{l=0}^{1022} rir[b][t + l - 511] * sk[l]
#define CT 1024  // outputs per block
__global__ void __launch_bounds__(256) conv_kernel(const float* __restrict__ sk,
                                                   float* __restrict__ out) {
    __shared__ float s_rir[CT + 1024];  // window [t0-511, t0-511+2048)
    __shared__ float s_k[1024];
    int b = blockIdx.y;
    int t0 = blockIdx.x * CT;
    int tid = threadIdx.x;

    for (int i = tid; i < CT + 1024; i += 256) {
        int idx = t0 - 511 + i;
        s_rir[i] = (idx >= 0 && idx < RIRLEN) ? g_rir[(size_t)b * RIRLEN + idx] : 0.f;
    }
    for (int i = tid; i < 1024; i += 256) s_k[i] = (i < FLEN) ? sk[i] : 0.f;
    __syncthreads();

    int base = tid * 4;  // 0..1020
    float4 acc = make_float4(0.f, 0.f, 0.f, 0.f);
#pragma unroll 4
    for (int l = 0; l < 1024; l += 4) {
        float4 kv = *(const float4*)&s_k[l];
        float4 f0 = *(const float4*)&s_rir[base + l];
        float4 f1 = *(const float4*)&s_rir[base + l + 4];
        acc.x += kv.x * f0.x + kv.y * f0.y + kv.z * f0.z + kv.w * f0.w;
        acc.y += kv.x * f0.y + kv.y * f0.z + kv.z * f0.w + kv.w * f1.x;
        acc.z += kv.x * f0.z + kv.y * f0.w + kv.z * f1.x + kv.w * f1.y;
        acc.w += kv.x * f0.w + kv.y * f1.x + kv.z * f1.y + kv.w * f1.z;
    }
    int tbase = t0 + base;
    if (tbase + 0 < RIRLEN) out[(size_t)b * RIRLEN + tbase + 0] = acc.x;
    if (tbase + 1 < RIRLEN) out[(size_t)b * RIRLEN + tbase + 1] = acc.y;
    if (tbase + 2 < RIRLEN) out[(size_t)b * RIRLEN + tbase + 2] = acc.z;
    if (tbase + 3 < RIRLEN) out[(size_t)b * RIRLEN + tbase + 3] = acc.w;
}

// ---------------- launch ----------------
extern "C" void kernel_launch(void* const* d_in, const int* in_sizes, int n_in,
                              void* d_out, int out_size) {
    const float* surface_params = (const float*)d_in[0];  // [16,10]
    const float* dir_params     = (const float*)d_in[1];  // [128,10]
    const float* path_dirs      = (const float*)d_in[2];  // [8,4096,3]
    const float* source_kernel  = (const float*)d_in[3];  // [1023]
    const float* surf_interp    = (const float*)d_in[4];  // [10,512]
    const float* dir_interp     = (const float*)d_in[5];  // [10,512]
    const float* fib_points     = (const float*)d_in[6];  // [128,3]
    const int*   mask           = (const int*)d_in[7];    // [8,4096,16]
    const int*   delays         = (const int*)d_in[8];    // [8,4096]
    float* out = (float*)d_out;                           // [8,96000]

    zero_rir_kernel<<<(B_SZ * RIRLEN + 1023) / 1024, 1024>>>();
    pre_small_kernel<<<5, 256>>>(surface_params, dir_params);
    pre_twiddle_kernel<<<1024, 256>>>();
    pre_T_kernel<<<40, 256>>>(surf_interp, dir_interp);
    pre_G_kernel<<<40, 256>>>();
    fr_kernel<<<NPATH, 128>>>(path_dirs, surf_interp, dir_interp, fib_points, mask, delays);
    dft_gemm_kernel<<<dim3(512 / GN, NPATH / GM, 2), 256>>>();
    scatter_kernel<<<NPATH, 256>>>(delays);
    conv_kernel<<<dim3((RIRLEN + CT - 1) / CT, B_SZ), 256>>>(source_kernel, out);
}

// round 3
// speedup vs baseline: 1.7067x; 1.7067x over previous
#include <cuda_runtime.h>
#include <cuda_bf16.h>
#include <math.h>
#include <stdint.h>

// ---------------- problem constants ----------------
#define B_SZ 8
#define P_SZ 4096
#define NPATH (B_SZ * P_SZ)      // 32768
#define S_SZ 16
#define NFIB 128
#define NBAND 10
#define FLEN 1023
#define RIRLEN 96000
#define EPS 1e-9f

// ---------------- device scratch ----------------
__device__ float g_cosW[512 * 512];     // cos(2*pi*k*n/1023) (symmetric)
__device__ float g_sinW[512 * 512];     // sin(2*pi*k*n/1023) (symmetric)
__device__ float g_T[20 * 512];
__device__ float g_G[20 * 512];
__device__ float g_logrefl[S_SZ * NBAND];
__device__ float g_sigdir[NFIB * NBAND];
// bf16 hi/lo split operands for tensor-core DFT
__device__ __nv_bfloat16 g_ch[512 * 512], g_cl[512 * 512];
__device__ __nv_bfloat16 g_sh[512 * 512], g_sl[512 * 512];
__device__ __nv_bfloat16 g_reh[NPATH * 512], g_rel[NPATH * 512];
__device__ __nv_bfloat16 g_imh[NPATH * 512], g_iml[NPATH * 512];
__device__ float g_rir[B_SZ * RIRLEN];

// ---------------- small kernels ----------------
__global__ void zero_rir_kernel() {
    int i = blockIdx.x * blockDim.x + threadIdx.x;
    if (i < B_SZ * RIRLEN) g_rir[i] = 0.f;
}

__global__ void pre_small_kernel(const float* __restrict__ sp,
                                 const float* __restrict__ dp) {
    int i = blockIdx.x * blockDim.x + threadIdx.x;
    if (i < S_SZ * NBAND) {
        float s = 1.f / (1.f + expf(-sp[i]));
        g_logrefl[i] = logf(s <= EPS ? EPS : s);
    }
    if (i < NFIB * NBAND) {
        g_sigdir[i] = 1.f / (1.f + expf(-dp[i]));
    }
}

__global__ void pre_twiddle_kernel() {
    int i = blockIdx.x * blockDim.x + threadIdx.x;
    if (i >= 512 * 512) return;
    int k = i >> 9, n = i & 511;
    int m = (k * n) % FLEN;                 // exact
    float x = (float)m * (2.0f / 1023.0f);  // in [0,2)
    float s, c;
    sincospif(x, &s, &c);
    g_cosW[i] = c;
    g_sinW[i] = s;
    __nv_bfloat16 ch = __float2bfloat16(c);
    g_ch[i] = ch; g_cl[i] = __float2bfloat16(c - __bfloat162float(ch));
    __nv_bfloat16 sh = __float2bfloat16(s);
    g_sh[i] = sh; g_sl[i] = __float2bfloat16(s - __bfloat162float(sh));
}

// T[j][n] = row[0] + 2*sum_{k>=1} row[k]*cos(2 pi k n/N), one warp per output
__global__ void pre_T_kernel(const float* __restrict__ si,
                             const float* __restrict__ di) {
    int gw = (blockIdx.x * 256 + threadIdx.x) >> 5;
    int lane = threadIdx.x & 31;
    if (gw >= 20 * 512) return;
    int j = gw >> 9, n = gw & 511;
    const float* row = (j < 10) ? (si + j * 512) : (di + (j - 10) * 512);
    float acc = 0.f;
    for (int k = 1 + lane; k < 512; k += 32)
        acc += row[k] * g_cosW[n * 512 + k];   // symmetric index: coalesced
    acc *= 2.f;
#pragma unroll
    for (int o = 16; o; o >>= 1) acc += __shfl_xor_sync(0xffffffffu, acc, o);
    if (lane == 0) g_T[gw] = acc + row[0];
}

// G[j][q] = -(2/N)*sum_{n>=1} T[j][n]*sin(2 pi q n/N), one warp per output
__global__ void pre_G_kernel() {
    int gw = (blockIdx.x * 256 + threadIdx.x) >> 5;
    int lane = threadIdx.x & 31;
    if (gw >= 20 * 512) return;
    int j = gw >> 9, q = gw & 511;
    float acc = 0.f;
    for (int n = 1 + lane; n < 512; n += 32)
        acc += g_T[j * 512 + n] * g_sinW[q * 512 + n];  // symmetric: coalesced
#pragma unroll
    for (int o = 16; o; o >>= 1) acc += __shfl_xor_sync(0xffffffffu, acc, o);
    if (lane == 0) g_G[gw] = acc * (-2.f / (float)FLEN);
}

// ---------------- per-path spectrum kernel ----------------
__global__ void __launch_bounds__(128) fr_kernel(
    const float* __restrict__ path_dirs,
    const float* __restrict__ surf_interp,
    const float* __restrict__ dir_interp,
    const float* __restrict__ fib,
    const int* __restrict__ mask,
    const int* __restrict__ delays) {
    int path = blockIdx.x;
    int t = threadIdx.x;

    __shared__ float sh_c[20];
    __shared__ float sh_w[128];
    __shared__ float sh_red[8];

    if (t < NBAND) {
        const int* m = mask + path * S_SZ;
        float acc = 0.f;
#pragma unroll
        for (int s = 0; s < S_SZ; s++) acc += (float)m[s] * g_logrefl[s * NBAND + t];
        sh_c[t] = acc;
    }

    float dx = path_dirs[path * 3 + 0];
    float dy = path_dirs[path * 3 + 1];
    float dz = path_dirs[path * 3 + 2];
    float inv = 1.f / (sqrtf(dx * dx + dy * dy + dz * dz) + EPS);
    dx *= inv; dy *= inv; dz *= inv;

    float logit = 8.f * (dx * fib[t * 3 + 0] + dy * fib[t * 3 + 1] + dz * fib[t * 3 + 2]);
    float v = logit;
#pragma unroll
    for (int o = 16; o; o >>= 1) v = fmaxf(v, __shfl_xor_sync(0xffffffffu, v, o));
    if ((t & 31) == 0) sh_red[t >> 5] = v;
    __syncthreads();
    float mx = fmaxf(fmaxf(sh_red[0], sh_red[1]), fmaxf(sh_red[2], sh_red[3]));
    float e = expf(logit - mx);
    v = e;
#pragma unroll
    for (int o = 16; o; o >>= 1) v += __shfl_xor_sync(0xffffffffu, v, o);
    if ((t & 31) == 0) sh_red[4 + (t >> 5)] = v;
    __syncthreads();
    float tot = sh_red[4] + sh_red[5] + sh_red[6] + sh_red[7];
    sh_w[t] = e / tot;
    __syncthreads();

    if (t < NBAND) {
        float amp = 0.f;
        for (int n = 0; n < NFIB; n++) amp += sh_w[n] * g_sigdir[n * NBAND + t];
        sh_c[10 + t] = logf(amp <= EPS ? EPS : amp);
    }
    __syncthreads();

    int dly = delays[path];
    float gain = 1.f / fmaxf((float)dly * (1.f / 48.f), 1.f);
    float base_scale = gain * (1.f / (float)FLEN);

    for (int q = t; q < 512; q += 128) {
        float la = 0.f, ph = 0.f;
#pragma unroll
        for (int j = 0; j < 10; j++) la += sh_c[j] * surf_interp[j * 512 + q];
#pragma unroll
        for (int j = 0; j < 10; j++) la += sh_c[10 + j] * dir_interp[j * 512 + q];
#pragma unroll
        for (int j = 0; j < 20; j++) ph += sh_c[j] * g_G[j * 512 + q];
        float a = __expf(la) * base_scale * (q == 0 ? 1.f : 2.f);
        // manual 2-step range reduction, then fast sincos
        float kk = rintf(ph * 0.15915494309189535f);
        float phr = fmaf(-6.2831855f, kk, ph);
        phr = fmaf(1.7484555e-7f, kk, phr);
        float sn, cs;
        __sincosf(phr, &sn, &cs);
        float vr = a * cs;
        float vi = -a * sn;
        size_t o = (size_t)path * 512 + q;
        __nv_bfloat16 rh = __float2bfloat16(vr);
        g_reh[o] = rh; g_rel[o] = __float2bfloat16(vr - __bfloat162float(rh));
        __nv_bfloat16 ih = __float2bfloat16(vi);
        g_imh[o] = ih; g_iml[o] = __float2bfloat16(vi - __bfloat162float(ih));
    }
}

// ---------------- tensor-core DFT + fused scatter ----------------
// C = re*cosW, S = im*sinW; rir[dly+n] += C-S, rir[dly+1023-n] += C+S
// bf16 split: x ~= xh + xl ; acc += Ah*Bh + Ah*Bl + Al*Bh
#define GST 24  // smem row stride in bf16 (16 data + 8 pad)

#define LDSM4(r, addr)                                                      \
    asm volatile("ldmatrix.sync.aligned.m8n8.x4.shared.b16 {%0,%1,%2,%3}, [%4];" \
                 : "=r"((r)[0]), "=r"((r)[1]), "=r"((r)[2]), "=r"((r)[3])   \
                 : "r"(addr))

#define MMA_BF16(acc, a, b0, b1)                                            \
    asm volatile("mma.sync.aligned.m16n8k16.row.col.f32.bf16.bf16.f32 "     \
                 "{%0,%1,%2,%3}, {%4,%5,%6,%7}, {%8,%9}, {%0,%1,%2,%3};"    \
                 : "+f"((acc)[0]), "+f"((acc)[1]), "+f"((acc)[2]), "+f"((acc)[3]) \
                 : "r"((a)[0]), "r"((a)[1]), "r"((a)[2]), "r"((a)[3]),      \
                   "r"(b0), "r"(b1))

__global__ void __launch_bounds__(256, 1) gemm_scatter_kernel(
    const int* __restrict__ delays) {
    __shared__ __nv_bfloat16 sm[8 * 128 * GST];  // 49152 B exactly
    // tiles: 0 reh, 1 rel, 2 imh, 3 iml, 4 ch, 5 cl, 6 sh, 7 sl
    int tid = threadIdx.x;
    int wid = tid >> 5, lane = tid & 31;
    int wm = (wid & 3) * 32;
    int wn = (wid >> 2) * 64;
    int rowBase = blockIdx.y * 128;
    int colBase = blockIdx.x * 128;

    const __nv_bfloat16* gsrc[8] = {g_reh, g_rel, g_imh, g_iml, g_ch, g_cl, g_sh, g_sl};
    int lr = tid >> 1;
    int lc = (tid & 1) * 8;

    float accC[2][8][4];
    float accS[2][8][4];
#pragma unroll
    for (int mt = 0; mt < 2; mt++)
#pragma unroll
        for (int nt = 0; nt < 8; nt++)
#pragma unroll
            for (int r = 0; r < 4; r++) { accC[mt][nt][r] = 0.f; accS[mt][nt][r] = 0.f; }

    unsigned smbase = (unsigned)__cvta_generic_to_shared(sm);
    int sel = lane >> 3, fr8 = lane & 7;
    int a_row_off = ((sel & 1) << 3) + fr8;
    int a_koff = (sel >> 1) << 3;
    int b_row_off = ((sel >> 1) << 3) + fr8;
    int b_koff = (sel & 1) << 3;

    uint4 ld[8];
#pragma unroll
    for (int t = 0; t < 8; t++) {
        int gr = (t < 4 ? rowBase : colBase) + lr;
        ld[t] = *(const uint4*)(gsrc[t] + (size_t)gr * 512 + lc);
    }

    for (int k0 = 0; k0 < 512; k0 += 16) {
#pragma unroll
        for (int t = 0; t < 8; t++)
            *(uint4*)((char*)sm + ((t * 128 + lr) * GST + lc) * 2) = ld[t];
        __syncthreads();
        if (k0 + 16 < 512) {
#pragma unroll
            for (int t = 0; t < 8; t++) {
                int gr = (t < 4 ? rowBase : colBase) + lr;
                ld[t] = *(const uint4*)(gsrc[t] + (size_t)gr * 512 + (k0 + 16) + lc);
            }
        }
        // A fragments for all 4 A-matrices x 2 m-tiles
        uint32_t af[4][2][4];
#pragma unroll
        for (int mat = 0; mat < 4; mat++)
#pragma unroll
            for (int mt = 0; mt < 2; mt++) {
                int row = wm + mt * 16 + a_row_off;
                unsigned addr = smbase + ((mat * 128 + row) * GST + a_koff) * 2;
                LDSM4(af[mat][mt], addr);
            }
#pragma unroll
        for (int g = 0; g < 4; g++) {
            uint32_t bf[4][4];
#pragma unroll
            for (int mat = 0; mat < 4; mat++) {
                int row = wn + g * 16 + b_row_off;
                unsigned addr = smbase + (((4 + mat) * 128 + row) * GST + b_koff) * 2;
                LDSM4(bf[mat], addr);
            }
#pragma unroll
            for (int mt = 0; mt < 2; mt++) {
#pragma unroll
                for (int j = 0; j < 2; j++) {
                    int nt = g * 2 + j;
                    MMA_BF16(accC[mt][nt], af[0][mt], bf[0][2 * j], bf[0][2 * j + 1]); // reh*ch
                    MMA_BF16(accC[mt][nt], af[0][mt], bf[1][2 * j], bf[1][2 * j + 1]); // reh*cl
                    MMA_BF16(accC[mt][nt], af[1][mt], bf[0][2 * j], bf[0][2 * j + 1]); // rel*ch
                    MMA_BF16(accS[mt][nt], af[2][mt], bf[2][2 * j], bf[2][2 * j + 1]); // imh*sh
                    MMA_BF16(accS[mt][nt], af[2][mt], bf[3][2 * j], bf[3][2 * j + 1]); // imh*sl
                    MMA_BF16(accS[mt][nt], af[3][mt], bf[2][2 * j], bf[2][2 * j + 1]); // iml*sh
                }
            }
        }
        __syncthreads();
    }

    // epilogue: scatter into RIR with atomics
    int r0 = lane >> 2, cp = (lane & 3) * 2;
#pragma unroll
    for (int mt = 0; mt < 2; mt++) {
#pragma unroll
        for (int half = 0; half < 2; half++) {
            int path = rowBase + wm + mt * 16 + half * 8 + r0;
            int dly = delays[path];
            float* rir = g_rir + (size_t)(path >> 12) * RIRLEN + dly;
#pragma unroll
            for (int nt = 0; nt < 8; nt++) {
                int n = colBase + wn + nt * 8 + cp;
                float c0 = accC[mt][nt][half * 2 + 0], s0 = accS[mt][nt][half * 2 + 0];
                float c1 = accC[mt][nt][half * 2 + 1], s1 = accS[mt][nt][half * 2 + 1];
                atomicAdd(rir + n, c0 - s0);
                atomicAdd(rir + n + 1, c1 - s1);
                if (n > 0) atomicAdd(rir + FLEN - n, c0 + s0);
                atomicAdd(rir + FLEN - (n + 1), c1 + s1);
            }
        }
    }
}

// ---------------- 'same' cross-correlation with source kernel ----------------
#define CT 1024
__global__ void __launch_bounds__(256) conv_kernel(const float* __restrict__ sk,
                                                   float* __restrict__ out) {
    __shared__ float s_rir[CT + 1024];
    __shared__ float s_k[1024];
    int b = blockIdx.y;
    int t0 = blockIdx.x * CT;
    int tid = threadIdx.x;

    for (int i = tid; i < CT + 1024; i += 256) {
        int idx = t0 - 511 + i;
        s_rir[i] = (idx >= 0 && idx < RIRLEN) ? g_rir[(size_t)b * RIRLEN + idx] : 0.f;
    }
    for (int i = tid; i < 1024; i += 256) s_k[i] = (i < FLEN) ? sk[i] : 0.f;
    __syncthreads();

    int base = tid * 4;
    float4 acc = make_float4(0.f, 0.f, 0.f, 0.f);
#pragma unroll 4
    for (int l = 0; l < 1024; l += 4) {
        float4 kv = *(const float4*)&s_k[l];
        float4 f0 = *(const float4*)&s_rir[base + l];
        float4 f1 = *(const float4*)&s_rir[base + l + 4];
        acc.x += kv.x * f0.x + kv.y * f0.y + kv.z * f0.z + kv.w * f0.w;
        acc.y += kv.x * f0.y + kv.y * f0.z + kv.z * f0.w + kv.w * f1.x;
        acc.z += kv.x * f0.z + kv.y * f0.w + kv.z * f1.x + kv.w * f1.y;
        acc.w += kv.x * f0.w + kv.y * f1.x + kv.z * f1.y + kv.w * f1.z;
    }
    int tbase = t0 + base;
    if (tbase + 0 < RIRLEN) out[(size_t)b * RIRLEN + tbase + 0] = acc.x;
    if (tbase + 1 < RIRLEN) out[(size_t)b * RIRLEN + tbase + 1] = acc.y;
    if (tbase + 2 < RIRLEN) out[(size_t)b * RIRLEN + tbase + 2] = acc.z;
    if (tbase + 3 < RIRLEN) out[(size_t)b * RIRLEN + tbase + 3] = acc.w;
}

// ---------------- launch ----------------
extern "C" void kernel_launch(void* const* d_in, const int* in_sizes, int n_in,
                              void* d_out, int out_size) {
    const float* surface_params = (const float*)d_in[0];
    const float* dir_params     = (const float*)d_in[1];
    const float* path_dirs      = (const float*)d_in[2];
    const float* source_kernel  = (const float*)d_in[3];
    const float* surf_interp    = (const float*)d_in[4];
    const float* dir_interp     = (const float*)d_in[5];
    const float* fib_points     = (const float*)d_in[6];
    const int*   mask           = (const int*)d_in[7];
    const int*   delays         = (const int*)d_in[8];
    float* out = (float*)d_out;

    zero_rir_kernel<<<(B_SZ * RIRLEN + 1023) / 1024, 1024>>>();
    pre_small_kernel<<<5, 256>>>(surface_params, dir_params);
    pre_twiddle_kernel<<<1024, 256>>>();
    pre_T_kernel<<<1280, 256>>>(surf_interp, dir_interp);
    pre_G_kernel<<<1280, 256>>>();
    fr_kernel<<<NPATH, 128>>>(path_dirs, surf_interp, dir_interp, fib_points, mask, delays);
    gemm_scatter_kernel<<<dim3(4, 256, 1), 256>>>(delays);
    conv_kernel<<<dim3((RIRLEN + CT - 1) / CT, B_SZ), 256>>>(source_kernel, out);
}